// round 5
// baseline (speedup 1.0000x reference)
#include <cuda_runtime.h>
#include <cuda_bf16.h>
#include <cstdint>

#define INPUT_DIM 16384
#define EMB 1024
#define BATCH 4096
#define XS_N (INPUT_DIM + EMB)      // 17408 floats: pad-to-2 upper bound (<32768, fits 15 bits)

// ---------------- device scratch ----------------
__device__ unsigned short g_comb[INPUT_DIM];                 // e | (neg<<15) per feature j
__device__ __align__(16) unsigned short g_pos[INPUT_DIM];    // padded slot | (neg<<15), by j
__device__ __align__(16) unsigned short g_sched[EMB];        // bucket ids, sorted by length desc
__device__ int g_astart[EMB];                                // pad-2 bucket start
__device__ int g_len[EMB];                                   // actual bucket length

// ---------------- K1: extract (bucket, sign) per feature row, early-exit ----------------
__global__ void k_extract(const float* __restrict__ hp) {
    int warp = (blockIdx.x * blockDim.x + threadIdx.x) >> 5;
    int lane = threadIdx.x & 31;
    if (warp >= INPUT_DIM) return;

    const float4* row = reinterpret_cast<const float4*>(hp + (size_t)warp * EMB);
    int my_e = 0; unsigned my_neg = 0;
    unsigned mask = 0;
    for (int i = 0; i < 8; i++) {                  // 8 chunks of 128 cols
        int idx4 = lane + i * 32;
        float4 v = row[idx4];
        int base = idx4 * 4;
        bool has = false;
        if (v.x != 0.0f) { my_e = base + 0; my_neg = (v.x < 0.0f); has = true; }
        if (v.y != 0.0f) { my_e = base + 1; my_neg = (v.y < 0.0f); has = true; }
        if (v.z != 0.0f) { my_e = base + 2; my_neg = (v.z < 0.0f); has = true; }
        if (v.w != 0.0f) { my_e = base + 3; my_neg = (v.w < 0.0f); has = true; }
        mask = __ballot_sync(0xffffffffu, has);
        if (mask) break;                           // uniform: whole warp exits together
    }
    if (mask == 0) { if (lane == 0) g_comb[warp] = 0; return; }
    int src = __ffs(mask) - 1;
    int e        = __shfl_sync(0xffffffffu, my_e, src);
    unsigned neg = __shfl_sync(0xffffffffu, my_neg, src);
    if (lane == 0) g_comb[warp] = (unsigned short)(e | (neg << 15));
}

// ---------------- K2: single-block build — histogram, scan, sort, slot assign ----------------
__global__ __launch_bounds__(EMB, 1)
void k_build() {
    __shared__ int hist[EMB];
    __shared__ int scn[EMB];
    __shared__ int cur[EMB];
    __shared__ int hc[128];
    __shared__ int hoff[128];
    int t = threadIdx.x;

    hist[t] = 0;
    if (t < 128) { hc[t] = 0; }
    __syncthreads();

    // histogram over g_comb (coalesced u16 reads, smem atomics)
#pragma unroll
    for (int i = 0; i < INPUT_DIM / EMB; i++) {
        unsigned c = g_comb[i * EMB + t];
        atomicAdd(&hist[c & (EMB - 1)], 1);
    }
    __syncthreads();

    int c  = hist[t];
    int pl = (c + 1) & ~1;                 // pad to multiple of 2

    // inclusive scan of padded lengths
    scn[t] = pl;
    __syncthreads();
#pragma unroll
    for (int off = 1; off < EMB; off <<= 1) {
        int a = (t >= off) ? scn[t - off] : 0;
        __syncthreads();
        scn[t] += a;
        __syncthreads();
    }
    int start = scn[t] - pl;
    g_astart[t] = start;
    g_len[t]    = c;
    cur[t]      = start;

    // counting sort of buckets by length, descending (key = 127 - clamped len)
    int key = 127 - (c > 127 ? 127 : c);
    atomicAdd(&hc[key], 1);
    __syncthreads();
    if (t < 128) hoff[t] = hc[t];          // save counts
    __syncthreads();
#pragma unroll
    for (int off = 1; off < 128; off <<= 1) {
        int a = 0;
        if (t < 128 && t >= off) a = hc[t - off];
        __syncthreads();
        if (t < 128) hc[t] += a;
        __syncthreads();
    }
    if (t < 128) hoff[t] = hc[t] - hoff[t];  // exclusive start -> cursor
    __syncthreads();
    int rank = atomicAdd(&hoff[key], 1);
    g_sched[rank] = (unsigned short)t;
    __syncthreads();

    // assign each feature its slot inside its bucket
#pragma unroll
    for (int i = 0; i < INPUT_DIM / EMB; i++) {
        int j = i * EMB + t;
        unsigned cb = g_comb[j];
        int pos = atomicAdd(&cur[cb & (EMB - 1)], 1);
        g_pos[j] = (unsigned short)(pos | (cb & 0x8000u));
    }
}

// ---------------- K3: main kernel — scatter-on-stage, balanced f2 reduce ----------------
#define GTHREADS 512
__global__ __launch_bounds__(GTHREADS, 3)
void k_gather(const float* __restrict__ x, float* __restrict__ out) {
    extern __shared__ float xs[];          // [XS_N] bucket-sorted signed row, then ores[EMB]
    float* ores = xs + XS_N;

    int b = blockIdx.x;
    int t = threadIdx.x;

    // Phase A: zero the (<=1) pad slot of odd-length buckets
#pragma unroll
    for (int r = 0; r < EMB / GTHREADS; r++) {
        int e  = t + r * GTHREADS;
        int l  = __ldg(&g_len[e]);
        if (l & 1) xs[__ldg(&g_astart[e]) + l] = 0.0f;
    }

    // Phase B: coalesced row load + permuted, sign-applied smem scatter
    {
        const float4* gx = reinterpret_cast<const float4*>(x + (size_t)b * INPUT_DIM);
        const uint2*  gp = reinterpret_cast<const uint2*>(g_pos);
#pragma unroll
        for (int i = t; i < INPUT_DIM / 4; i += GTHREADS) {
            float4 v = gx[i];
            uint2  p = gp[i];
            unsigned p0 = p.x & 0xFFFFu, p1 = p.x >> 16;
            unsigned p2 = p.y & 0xFFFFu, p3 = p.y >> 16;
            xs[p0 & 0x7FFFu] = __uint_as_float(__float_as_uint(v.x) ^ ((p0 & 0x8000u) << 16));
            xs[p1 & 0x7FFFu] = __uint_as_float(__float_as_uint(v.y) ^ ((p1 & 0x8000u) << 16));
            xs[p2 & 0x7FFFu] = __uint_as_float(__float_as_uint(v.z) ^ ((p2 & 0x8000u) << 16));
            xs[p3 & 0x7FFFu] = __uint_as_float(__float_as_uint(v.w) ^ ((p3 & 0x8000u) << 16));
        }
    }
    __syncthreads();

    // Phase C: balanced per-bucket reduction (thread t: sorted[t] + sorted[1023-t])
#pragma unroll
    for (int r = 0; r < 2; r++) {
        int idx = (r == 0) ? t : (EMB - 1 - t);
        int e   = __ldg(&g_sched[idx]);
        int s0  = __ldg(&g_astart[e]);
        int n2  = (__ldg(&g_len[e]) + 1) >> 1;
        const float2* p2 = reinterpret_cast<const float2*>(xs) + (s0 >> 1);
        float acc = 0.0f;
        for (int i = 0; i < n2; i++) { float2 v = p2[i]; acc += v.x + v.y; }
        ores[e] = acc;
    }
    __syncthreads();

    // coalesced output
    if (t < EMB / 4) {
        reinterpret_cast<float4*>(out + (size_t)b * EMB)[t] =
            reinterpret_cast<const float4*>(ores)[t];
    }
}

extern "C" void kernel_launch(void* const* d_in, const int* in_sizes, int n_in,
                              void* d_out, int out_size) {
    const float* x  = (const float*)d_in[0];   // [BATCH, INPUT_DIM]
    const float* hp = (const float*)d_in[1];   // [INPUT_DIM, EMB]
    float* out = (float*)d_out;                // [BATCH, EMB]

    int smem = (XS_N + EMB) * (int)sizeof(float);   // 73728 B -> 3 blocks/SM
    cudaFuncSetAttribute(k_gather, cudaFuncAttributeMaxDynamicSharedMemorySize, smem);

    k_extract<<<(INPUT_DIM * 32) / 256, 256>>>(hp);
    k_build<<<1, EMB>>>();
    k_gather<<<BATCH, GTHREADS, smem>>>(x, out);
}